// round 7
// baseline (speedup 1.0000x reference)
#include <cuda_runtime.h>
#include <cstdint>

// ---------------- problem constants ----------------
#define B_      128
#define T_IN_   240
#define T_OUT_  30
#define D_      128
#define H_      256
#define G3_     768

#define ENC_LEN 30720   // T_IN * B
#define DEC_LEN 3840    // T_OUT * B

// segmentation: 3 chains per 4-CTA cluster
#define CHAINS   3
#define CHUNK    320     // 96 enc chains * 320 = 30720 ; 12 dec chains * 320 = 3840
#define WARMUP   160
#define STEPS    (CHUNK + WARMUP)   // 480
#define NCL_ENC  32
#define NCL_DEC  4

#define NTHREADS 416     // 12 matvec warps + 1 gate warp

// ---------------- device scratch ----------------
__device__ float g_gi_enc[(size_t)ENC_LEN * G3_];   // ~94 MB
__device__ float g_gi_dec[(size_t)DEC_LEN * G3_];   // ~12 MB

// ---------------- helpers ----------------
__device__ __forceinline__ uint32_t smem_u32(const void* p) {
    return (uint32_t)__cvta_generic_to_shared(p);
}
__device__ __forceinline__ uint32_t mapa_u32(uint32_t addr, uint32_t rank) {
    uint32_t d;
    asm("mapa.shared::cluster.u32 %0, %1, %2;" : "=r"(d) : "r"(addr), "r"(rank));
    return d;
}
__device__ __forceinline__ void cl_sync() {
    asm volatile("barrier.cluster.arrive.aligned;" ::: "memory");
    asm volatile("barrier.cluster.wait.aligned;"   ::: "memory");
}
__device__ __forceinline__ void mbar_init(uint32_t mbar, uint32_t count) {
    asm volatile("mbarrier.init.shared.b64 [%0], %1;" :: "r"(mbar), "r"(count) : "memory");
}
__device__ __forceinline__ void mbar_arrive_expect(uint32_t mbar, uint32_t bytes) {
    asm volatile("mbarrier.arrive.expect_tx.shared::cta.b64 _, [%0], %1;"
                 :: "r"(mbar), "r"(bytes) : "memory");
}
__device__ __forceinline__ void mbar_wait_parity(uint32_t mbar, uint32_t parity) {
    uint32_t done;
    asm volatile(
        "{\n\t.reg .pred p;\n\t"
        "mbarrier.try_wait.parity.acquire.cta.shared::cta.b64 p, [%1], %2;\n\t"
        "selp.b32 %0, 1, 0, p;\n\t}"
        : "=r"(done) : "r"(mbar), "r"(parity) : "memory");
    if (!done) {
        asm volatile(
            "{\n\t.reg .pred P1;\n\t"
            "WAIT_LOOP_%=:\n\t"
            "mbarrier.try_wait.parity.acquire.cta.shared::cta.b64 P1, [%0], %1, 0x989680;\n\t"
            "@P1 bra.uni WAIT_DONE_%=;\n\t"
            "bra.uni WAIT_LOOP_%=;\n\t"
            "WAIT_DONE_%=:\n\t}"
            :: "r"(mbar), "r"(parity) : "memory");
    }
}
__device__ __forceinline__ void st_async_f32(uint32_t addr, float v, uint32_t mbar) {
    asm volatile(
        "st.async.weak.shared::cluster.mbarrier::complete_tx::bytes.f32 [%0], %1, [%2];"
        :: "r"(addr), "f"(v), "r"(mbar) : "memory");
}
__device__ __forceinline__ void bar_arrive(int id, int cnt) {
    asm volatile("bar.arrive %0, %1;" :: "r"(id), "r"(cnt) : "memory");
}
__device__ __forceinline__ void bar_sync(int id, int cnt) {
    asm volatile("bar.sync %0, %1;" :: "r"(id), "r"(cnt) : "memory");
}
__device__ __forceinline__ unsigned long long ffma2(unsigned long long a,
                                                    unsigned long long b,
                                                    unsigned long long c) {
    unsigned long long r;
    asm("fma.rn.f32x2 %0, %1, %2, %3;" : "=l"(r) : "l"(a), "l"(b), "l"(c));
    return r;
}
__device__ __forceinline__ float f2lo(unsigned long long v) {
    return __uint_as_float((unsigned)(v & 0xffffffffull));
}
__device__ __forceinline__ float f2hi(unsigned long long v) {
    return __uint_as_float((unsigned)(v >> 32));
}
__device__ __forceinline__ float sig_(float x) { return 1.0f / (1.0f + __expf(-x)); }
__device__ __forceinline__ float th_(float x)  { return 2.0f / (1.0f + __expf(-2.0f * x)) - 1.0f; }

// ============================================================
// Phase 1: GI = X @ Wih^T + bih  (unchanged — verified)
// ============================================================
__global__ __launch_bounds__(256)
void gi_gemm(const float* __restrict__ x,
             const float* __restrict__ Wih_e, const float* __restrict__ bih_e,
             const float* __restrict__ Wih_d, const float* __restrict__ bih_d)
{
    __shared__ float Xs[64][68];   // [k][pos]
    __shared__ float Ws[64][68];   // [k][gate]

    const int tileP = blockIdx.x;
    const bool enc = (tileP < (ENC_LEN / 64));
    const float* __restrict__ Wih = enc ? Wih_e : Wih_d;
    const float* __restrict__ bih = enc ? bih_e : bih_d;
    float* __restrict__ gout = enc ? g_gi_enc : g_gi_dec;
    const int p0 = (enc ? tileP : (tileP - ENC_LEN / 64)) * 64;
    const int g0 = blockIdx.y * 64;
    const int tid = threadIdx.x;
    const int tstride = enc ? 1 : 8;

    const int tx = tid & 15;
    const int ty = tid >> 4;
    float acc[4][4] = {};

    for (int kc = 0; kc < 2; ++kc) {
        #pragma unroll
        for (int i = tid; i < 64 * 64; i += 256) {
            int pos = i >> 6, k = i & 63;
            int p = p0 + pos;
            int b = p & 127, t = (p >> 7) * tstride;
            Xs[k][pos] = x[((size_t)b * T_IN_ + t) * D_ + kc * 64 + k];
        }
        #pragma unroll
        for (int i = tid; i < 64 * 64; i += 256) {
            int g = i >> 6, k = i & 63;
            Ws[k][g] = Wih[(size_t)(g0 + g) * D_ + kc * 64 + k];
        }
        __syncthreads();

        #pragma unroll 16
        for (int k = 0; k < 64; ++k) {
            float4 a = *(const float4*)&Xs[k][ty * 4];
            float4 b = *(const float4*)&Ws[k][tx * 4];
            float av[4] = {a.x, a.y, a.z, a.w};
            float bv[4] = {b.x, b.y, b.z, b.w};
            #pragma unroll
            for (int i = 0; i < 4; ++i)
                #pragma unroll
                for (int j = 0; j < 4; ++j)
                    acc[i][j] = fmaf(av[i], bv[j], acc[i][j]);
        }
        __syncthreads();
    }

    float bz[4];
    #pragma unroll
    for (int j = 0; j < 4; ++j) bz[j] = bih[g0 + tx * 4 + j];

    #pragma unroll
    for (int i = 0; i < 4; ++i) {
        int p = p0 + ty * 4 + i;
        float4 o;
        o.x = acc[i][0] + bz[0];
        o.y = acc[i][1] + bz[1];
        o.z = acc[i][2] + bz[2];
        o.w = acc[i][3] + bz[3];
        *(float4*)&gout[(size_t)p * G3_ + g0 + tx * 4] = o;
    }
}

// ============================================================
// Phase 2: segmented GRU scan — warp-specialized.
//   warps 0-5  : rows 0..191, half 0 (h[0..127])   broadcast LDS
//   warps 6-11 : rows 0..191, half 1 (h[128..255])
//   warp 12    : gate warp — 2 coords/thread; gates, st.async, arms
// 3 chains per cluster, round-robin: gates+DSMEM of chain c hide
// under matvecs of chains c+1, c+2.
// ============================================================
__global__ __launch_bounds__(NTHREADS, 1) __cluster_dims__(4, 1, 1)
void gru_scan(const float* __restrict__ Whh_e, const float* __restrict__ bhh_e,
              const float* __restrict__ Whh_d, const float* __restrict__ bhh_d,
              float* __restrict__ out)
{
    __shared__ __align__(16) float hbuf[2][CHAINS][256];   // [parity][chain][H]
    __shared__ float sGHp[CHAINS][2][192];                 // [chain][half][row]
    __shared__ float sGI[CHAINS][192];
    __shared__ float sBH[192];
    __shared__ __align__(8) unsigned long long mbars[CHAINS][2];

    const int tid  = threadIdx.x;
    const int warp = tid >> 5;
    const int lane = tid & 31;
    uint32_t rank;
    asm("mov.u32 %0, %%cluster_ctarank;" : "=r"(rank));

    const int cl   = blockIdx.x >> 2;
    const bool enc = cl < NCL_ENC;
    const int lcl  = enc ? cl : cl - NCL_ENC;
    const float* __restrict__ Whh = enc ? Whh_e : Whh_d;
    const float* __restrict__ bhh = enc ? bhh_e : bhh_d;
    const float* __restrict__ gi  = enc ? g_gi_enc : g_gi_dec;

    int base[CHAINS];
    #pragma unroll
    for (int c = 0; c < CHAINS; ++c)
        base[c] = (lcl * CHAINS + c) * CHUNK;

    const uint32_t mb_base = smem_u32(&mbars[0][0]);

    // ---- shared init ----
    for (int i = tid; i < 2 * CHAINS * 256; i += NTHREADS)
        ((float*)hbuf)[i] = 0.0f;
    if (tid < 192) {
        int g = tid >> 6, j = tid & 63;
        sBH[tid] = bhh[g * 256 + (int)rank * 64 + j];
    }
    if (tid == 0) {
        #pragma unroll
        for (int i = 0; i < 2 * CHAINS; ++i) mbar_init(mb_base + i * 8, 1);
    }
    __syncthreads();
    cl_sync();   // barriers + zeroed buffers visible cluster-wide

    if (warp < 12) {
        // ================= MATVEC WARPS =================
        const int half = (warp >= 6) ? 1 : 0;
        const int row  = ((half ? warp - 6 : warp) << 5) + lane;   // 0..191
        const int gate = row >> 6;
        const int jl   = row & 63;
        const int Rg   = gate * 256 + (int)rank * 64 + jl;

        // 128 weights in registers (64 packed f32x2)
        unsigned long long w[64];
        {
            const ulonglong2* wsrc =
                (const ulonglong2*)(Whh + (size_t)Rg * H_ + half * 128);
            #pragma unroll
            for (int i = 0; i < 32; ++i) {
                ulonglong2 t = wsrc[i];
                w[2 * i]     = t.x;
                w[2 * i + 1] = t.y;
            }
        }

        // per-chain gi pointers (advance only when inside the sequence)
        const size_t gi_off = (size_t)gate * 256 + rank * 64 + jl;
        const float* gp[CHAINS];
        float gin[CHAINS];
        #pragma unroll
        for (int c = 0; c < CHAINS; ++c) {
            int p0 = base[c] - WARMUP; if (p0 < 0) p0 = 0;
            gp[c] = gi + (size_t)p0 * G3_ + gi_off;
            gin[c] = (half == 0) ? __ldg(gp[c]) : 0.0f;
        }

        uint32_t mph[2] = {0u, 0u};

        for (int s = 0; s < STEPS; ++s) {
            const int ph = s & 1;
            #pragma unroll
            for (int c = 0; c < CHAINS; ++c) {
                if (s > 0)
                    mbar_wait_parity(mb_base + (c * 2 + ph) * 8, mph[ph] & 1u);

                float giv = gin[c];
                // prefetch next step's gi (guarded: last step has no next row)
                if (half == 0 && s + 1 < STEPS) {
                    if (base[c] + s + 1 > WARMUP) gp[c] += G3_;
                    gin[c] = __ldg(gp[c]);
                }

                const ulonglong2* h2 =
                    (const ulonglong2*)(&hbuf[ph][c][0] + (half << 7));
                unsigned long long a0 = 0ull, a1 = 0ull, a2 = 0ull, a3 = 0ull;
                #pragma unroll
                for (int i = 0; i < 16; ++i) {
                    ulonglong2 hva = h2[2 * i];
                    ulonglong2 hvb = h2[2 * i + 1];
                    a0 = ffma2(w[4 * i],     hva.x, a0);
                    a1 = ffma2(w[4 * i + 1], hva.y, a1);
                    a2 = ffma2(w[4 * i + 2], hvb.x, a2);
                    a3 = ffma2(w[4 * i + 3], hvb.y, a3);
                }
                float sum = (f2lo(a0) + f2hi(a0)) + (f2lo(a1) + f2hi(a1))
                          + (f2lo(a2) + f2hi(a2)) + (f2lo(a3) + f2hi(a3));
                sGHp[c][half][row] = sum;
                if (half == 0) sGI[c][row] = giv;
                bar_arrive(1 + c, NTHREADS);
            }
            if (s > 0) mph[ph]++;
        }
    } else {
        // ================= GATE WARP =================
        // peer addresses
        uint32_t my_hb = smem_u32(&hbuf[0][0][0]);
        uint32_t peer_hb[4], peer_mb[4];
        #pragma unroll
        for (int r = 0; r < 4; ++r) {
            peer_hb[r] = mapa_u32(my_hb, r);
            peer_mb[r] = mapa_u32(mb_base, r);
        }
        const int j0 = lane;          // coords j0 and j0+32

        for (int s = 0; s < STEPS; ++s) {
            const int ph = s & 1;
            #pragma unroll
            for (int c = 0; c < CHAINS; ++c) {
                // arm mbar[c][ph^1] for this sub-step's h'(s+1) stores
                if (lane == 0 && s + 1 < STEPS)
                    mbar_arrive_expect(mb_base + (c * 2 + (ph ^ 1)) * 8, 1024);

                bar_sync(1 + c, NTHREADS);   // matvec partials ready

                const int p = base[c] + s - WARMUP;
                #pragma unroll
                for (int q = 0; q < 2; ++q) {
                    const int j = j0 + q * 32;
                    float ghr = sGHp[c][0][j]       + sGHp[c][1][j]       + sBH[j];
                    float ghz = sGHp[c][0][64 + j]  + sGHp[c][1][64 + j]  + sBH[64 + j];
                    float ghn = sGHp[c][0][128 + j] + sGHp[c][1][128 + j] + sBH[128 + j];
                    float r_ = sig_(sGI[c][j]       + ghr);
                    float z_ = sig_(sGI[c][64 + j]  + ghz);
                    float n_ = th_ (sGI[c][128 + j] + r_ * ghn);
                    float hold = hbuf[ph][c][(int)rank * 64 + j];
                    float hn = (1.0f - z_) * n_ + z_ * hold;
                    if (p < 0) hn = 0.0f;   // pre-sequence region of segment 0

                    if (s + 1 < STEPS) {
                        uint32_t boff = (uint32_t)((((ph ^ 1) * CHAINS + c) << 8)
                                                   + (int)rank * 64 + j) * 4u;
                        uint32_t moff = (uint32_t)(c * 2 + (ph ^ 1)) * 8u;
                        #pragma unroll
                        for (int r = 0; r < 4; ++r)
                            st_async_f32(peer_hb[r] + boff, hn, peer_mb[r] + moff);
                    }

                    if (s >= WARMUP) {
                        if (enc) {
                            if ((p & 127) == 127) {
                                int t_out = p >> 7;
                                out[(size_t)t_out * H_ + rank * 64 + j] = hn;
                            }
                        } else {
                            int b = p & 127, t = p >> 7;
                            out[(size_t)(T_IN_ * H_) +
                                ((size_t)b * T_OUT_ + t) * H_ + rank * 64 + j] = hn;
                        }
                    }
                }
            }
        }
    }

    cl_sync();   // drain async traffic before cluster teardown
}

// ============================================================
// launch
// ============================================================
extern "C" void kernel_launch(void* const* d_in, const int* in_sizes, int n_in,
                              void* d_out, int out_size)
{
    const float* x     = (const float*)d_in[0];
    const float* Wih_e = (const float*)d_in[1];
    const float* Whh_e = (const float*)d_in[2];
    const float* bih_e = (const float*)d_in[3];
    const float* bhh_e = (const float*)d_in[4];
    const float* Wih_d = (const float*)d_in[5];
    const float* Whh_d = (const float*)d_in[6];
    const float* bih_d = (const float*)d_in[7];
    const float* bhh_d = (const float*)d_in[8];
    float* out = (float*)d_out;

    dim3 ggrid(ENC_LEN / 64 + DEC_LEN / 64, G3_ / 64);  // (540, 12)
    gi_gemm<<<ggrid, 256>>>(x, Wih_e, bih_e, Wih_d, bih_d);

    gru_scan<<<(NCL_ENC + NCL_DEC) * 4, NTHREADS>>>(
        Whh_e, bhh_e, Whh_d, bhh_d, out);
}

// round 8
// speedup vs baseline: 1.2380x; 1.2380x over previous
#include <cuda_runtime.h>
#include <cstdint>

// ---------------- problem constants ----------------
#define B_      128
#define T_IN_   240
#define T_OUT_  30
#define D_      128
#define H_      256
#define G3_     768

#define ENC_LEN 30720   // T_IN * B
#define DEC_LEN 3840    // T_OUT * B

// segmentation: 3 chains per 4-CTA cluster
#define CHAINS   3
#define CHUNK    320     // 96 enc chains * 320 = 30720 ; 12 dec chains * 320 = 3840
#define WARMUP   160
#define STEPS    (CHUNK + WARMUP)   // 480
#define NCL_ENC  32
#define NCL_DEC  4

#define NTHREADS 384     // 12 warps; warps 0..2 double as gate warps

// ---------------- device scratch ----------------
__device__ float g_gi_enc[(size_t)ENC_LEN * G3_];   // ~94 MB
__device__ float g_gi_dec[(size_t)DEC_LEN * G3_];   // ~12 MB

// ---------------- helpers ----------------
__device__ __forceinline__ uint32_t smem_u32(const void* p) {
    return (uint32_t)__cvta_generic_to_shared(p);
}
__device__ __forceinline__ uint32_t mapa_u32(uint32_t addr, uint32_t rank) {
    uint32_t d;
    asm("mapa.shared::cluster.u32 %0, %1, %2;" : "=r"(d) : "r"(addr), "r"(rank));
    return d;
}
__device__ __forceinline__ void cl_sync() {
    asm volatile("barrier.cluster.arrive.aligned;" ::: "memory");
    asm volatile("barrier.cluster.wait.aligned;"   ::: "memory");
}
__device__ __forceinline__ void mbar_init(uint32_t mbar, uint32_t count) {
    asm volatile("mbarrier.init.shared.b64 [%0], %1;" :: "r"(mbar), "r"(count) : "memory");
}
__device__ __forceinline__ void mbar_arrive_expect(uint32_t mbar, uint32_t bytes) {
    asm volatile("mbarrier.arrive.expect_tx.shared::cta.b64 _, [%0], %1;"
                 :: "r"(mbar), "r"(bytes) : "memory");
}
__device__ __forceinline__ void mbar_wait_parity(uint32_t mbar, uint32_t parity) {
    uint32_t done;
    asm volatile(
        "{\n\t.reg .pred p;\n\t"
        "mbarrier.try_wait.parity.acquire.cta.shared::cta.b64 p, [%1], %2;\n\t"
        "selp.b32 %0, 1, 0, p;\n\t}"
        : "=r"(done) : "r"(mbar), "r"(parity) : "memory");
    if (!done) {
        asm volatile(
            "{\n\t.reg .pred P1;\n\t"
            "WAIT_LOOP_%=:\n\t"
            "mbarrier.try_wait.parity.acquire.cta.shared::cta.b64 P1, [%0], %1, 0x989680;\n\t"
            "@P1 bra.uni WAIT_DONE_%=;\n\t"
            "bra.uni WAIT_LOOP_%=;\n\t"
            "WAIT_DONE_%=:\n\t}"
            :: "r"(mbar), "r"(parity) : "memory");
    }
}
__device__ __forceinline__ void st_async_f32(uint32_t addr, float v, uint32_t mbar) {
    asm volatile(
        "st.async.weak.shared::cluster.mbarrier::complete_tx::bytes.f32 [%0], %1, [%2];"
        :: "r"(addr), "f"(v), "r"(mbar) : "memory");
}
__device__ __forceinline__ void bar_arrive(int id, int cnt) {
    asm volatile("bar.arrive %0, %1;" :: "r"(id), "r"(cnt) : "memory");
}
__device__ __forceinline__ void bar_sync(int id, int cnt) {
    asm volatile("bar.sync %0, %1;" :: "r"(id), "r"(cnt) : "memory");
}
__device__ __forceinline__ unsigned long long ffma2(unsigned long long a,
                                                    unsigned long long b,
                                                    unsigned long long c) {
    unsigned long long r;
    asm("fma.rn.f32x2 %0, %1, %2, %3;" : "=l"(r) : "l"(a), "l"(b), "l"(c));
    return r;
}
__device__ __forceinline__ float f2lo(unsigned long long v) {
    return __uint_as_float((unsigned)(v & 0xffffffffull));
}
__device__ __forceinline__ float f2hi(unsigned long long v) {
    return __uint_as_float((unsigned)(v >> 32));
}
__device__ __forceinline__ float sig_(float x) { return 1.0f / (1.0f + __expf(-x)); }
__device__ __forceinline__ float th_(float x)  { return 2.0f / (1.0f + __expf(-2.0f * x)) - 1.0f; }

// ============================================================
// Phase 1: GI = X @ Wih^T + bih  (unchanged — verified)
// ============================================================
__global__ __launch_bounds__(256)
void gi_gemm(const float* __restrict__ x,
             const float* __restrict__ Wih_e, const float* __restrict__ bih_e,
             const float* __restrict__ Wih_d, const float* __restrict__ bih_d)
{
    __shared__ float Xs[64][68];   // [k][pos]
    __shared__ float Ws[64][68];   // [k][gate]

    const int tileP = blockIdx.x;
    const bool enc = (tileP < (ENC_LEN / 64));
    const float* __restrict__ Wih = enc ? Wih_e : Wih_d;
    const float* __restrict__ bih = enc ? bih_e : bih_d;
    float* __restrict__ gout = enc ? g_gi_enc : g_gi_dec;
    const int p0 = (enc ? tileP : (tileP - ENC_LEN / 64)) * 64;
    const int g0 = blockIdx.y * 64;
    const int tid = threadIdx.x;
    const int tstride = enc ? 1 : 8;

    const int tx = tid & 15;
    const int ty = tid >> 4;
    float acc[4][4] = {};

    for (int kc = 0; kc < 2; ++kc) {
        #pragma unroll
        for (int i = tid; i < 64 * 64; i += 256) {
            int pos = i >> 6, k = i & 63;
            int p = p0 + pos;
            int b = p & 127, t = (p >> 7) * tstride;
            Xs[k][pos] = x[((size_t)b * T_IN_ + t) * D_ + kc * 64 + k];
        }
        #pragma unroll
        for (int i = tid; i < 64 * 64; i += 256) {
            int g = i >> 6, k = i & 63;
            Ws[k][g] = Wih[(size_t)(g0 + g) * D_ + kc * 64 + k];
        }
        __syncthreads();

        #pragma unroll 16
        for (int k = 0; k < 64; ++k) {
            float4 a = *(const float4*)&Xs[k][ty * 4];
            float4 b = *(const float4*)&Ws[k][tx * 4];
            float av[4] = {a.x, a.y, a.z, a.w};
            float bv[4] = {b.x, b.y, b.z, b.w};
            #pragma unroll
            for (int i = 0; i < 4; ++i)
                #pragma unroll
                for (int j = 0; j < 4; ++j)
                    acc[i][j] = fmaf(av[i], bv[j], acc[i][j]);
        }
        __syncthreads();
    }

    float bz[4];
    #pragma unroll
    for (int j = 0; j < 4; ++j) bz[j] = bih[g0 + tx * 4 + j];

    #pragma unroll
    for (int i = 0; i < 4; ++i) {
        int p = p0 + ty * 4 + i;
        float4 o;
        o.x = acc[i][0] + bz[0];
        o.y = acc[i][1] + bz[1];
        o.z = acc[i][2] + bz[2];
        o.w = acc[i][3] + bz[3];
        *(float4*)&gout[(size_t)p * G3_ + g0 + tx * 4] = o;
    }
}

// ============================================================
// Phase 2: segmented GRU scan — 12 warps, 168 regs (no spills).
//   warps 0-5  : rows 0..191, half 0 (h[0..127])  broadcast LDS
//   warps 6-11 : rows 0..191, half 1 (h[128..255])
//   warp c (c<3) additionally runs gates for chain c after
//   bar.sync(1+c): gates, st.async h' to 4 CTAs, outputs.
// Gates+DSMEM of chain c overlap matvecs of chains c+1, c+2.
// ============================================================
__global__ __launch_bounds__(NTHREADS, 1) __cluster_dims__(4, 1, 1)
void gru_scan(const float* __restrict__ Whh_e, const float* __restrict__ bhh_e,
              const float* __restrict__ Whh_d, const float* __restrict__ bhh_d,
              float* __restrict__ out)
{
    __shared__ __align__(16) float hbuf[2][CHAINS][256];   // [parity][chain][H]
    __shared__ float sGHp[CHAINS][2][192];                 // [chain][half][row]
    __shared__ float sGI[CHAINS][192];
    __shared__ float sBH[192];
    __shared__ __align__(8) unsigned long long mbars[CHAINS][2];

    const int tid  = threadIdx.x;
    const int warp = tid >> 5;
    const int lane = tid & 31;
    uint32_t rank;
    asm("mov.u32 %0, %%cluster_ctarank;" : "=r"(rank));

    const int cl   = blockIdx.x >> 2;
    const bool enc = cl < NCL_ENC;
    const int lcl  = enc ? cl : cl - NCL_ENC;
    const float* __restrict__ Whh = enc ? Whh_e : Whh_d;
    const float* __restrict__ bhh = enc ? bhh_e : bhh_d;
    const float* __restrict__ gi  = enc ? g_gi_enc : g_gi_dec;

    int base[CHAINS];
    #pragma unroll
    for (int c = 0; c < CHAINS; ++c)
        base[c] = (lcl * CHAINS + c) * CHUNK;

    const uint32_t mb_base = smem_u32(&mbars[0][0]);

    // ---- shared init ----
    for (int i = tid; i < 2 * CHAINS * 256; i += NTHREADS)
        ((float*)hbuf)[i] = 0.0f;
    if (tid < 192) {
        int g = tid >> 6, j = tid & 63;
        sBH[tid] = bhh[g * 256 + (int)rank * 64 + j];
    }
    if (tid == 0) {
        #pragma unroll
        for (int i = 0; i < 2 * CHAINS; ++i) mbar_init(mb_base + i * 8, 1);
    }
    __syncthreads();
    cl_sync();   // barriers + zeroed buffers visible cluster-wide

    // ---- thread mapping ----
    const int half = (warp >= 6) ? 1 : 0;
    const int row  = ((half ? warp - 6 : warp) << 5) + lane;   // 0..191
    const int gate = row >> 6;
    const int jl   = row & 63;
    const int Rg   = gate * 256 + (int)rank * 64 + jl;
    const bool is_gate_warp = (warp < CHAINS);
    const int gc = warp;              // gate chain index for warps 0..2

    // 128 weights in registers (64 packed f32x2)
    unsigned long long w[64];
    {
        const ulonglong2* wsrc =
            (const ulonglong2*)(Whh + (size_t)Rg * H_ + half * 128);
        #pragma unroll
        for (int i = 0; i < 32; ++i) {
            ulonglong2 t = wsrc[i];
            w[2 * i]     = t.x;
            w[2 * i + 1] = t.y;
        }
    }

    // peer addresses (used by gate warps only; cheap for all)
    uint32_t peer_hb[4], peer_mb[4];
    {
        uint32_t my_hb = smem_u32(&hbuf[0][0][0]);
        #pragma unroll
        for (int r = 0; r < 4; ++r) {
            peer_hb[r] = mapa_u32(my_hb, r);
            peer_mb[r] = mapa_u32(mb_base, r);
        }
    }

    // per-chain gi pointers (half-0 threads prefetch one step ahead)
    const size_t gi_off = (size_t)gate * 256 + rank * 64 + jl;
    const float* gp[CHAINS];
    float gin[CHAINS];
    #pragma unroll
    for (int c = 0; c < CHAINS; ++c) {
        int p0 = base[c] - WARMUP; if (p0 < 0) p0 = 0;
        gp[c] = gi + (size_t)p0 * G3_ + gi_off;
        gin[c] = (half == 0) ? __ldg(gp[c]) : 0.0f;
    }

    uint32_t mph[2] = {0u, 0u};

    for (int s = 0; s < STEPS; ++s) {
        const int ph = s & 1;
        #pragma unroll
        for (int c = 0; c < CHAINS; ++c) {
            if (s > 0)
                mbar_wait_parity(mb_base + (c * 2 + ph) * 8, mph[ph] & 1u);

            // gate warp arms mbar[c][ph^1] for THIS step's h' stores.
            // Safe: that barrier's previous phase completed at step s-1.
            if (is_gate_warp && gc == c && lane == 0 && s + 1 < STEPS)
                mbar_arrive_expect(mb_base + (c * 2 + (ph ^ 1)) * 8, 1024);

            float giv = gin[c];
            if (half == 0 && s + 1 < STEPS) {      // guarded prefetch
                if (base[c] + s + 1 > WARMUP) gp[c] += G3_;
                gin[c] = __ldg(gp[c]);
            }

            const ulonglong2* h2 =
                (const ulonglong2*)(&hbuf[ph][c][0] + (half << 7));
            unsigned long long a0 = 0ull, a1 = 0ull, a2 = 0ull, a3 = 0ull;
            #pragma unroll
            for (int i = 0; i < 16; ++i) {
                ulonglong2 hva = h2[2 * i];
                ulonglong2 hvb = h2[2 * i + 1];
                a0 = ffma2(w[4 * i],     hva.x, a0);
                a1 = ffma2(w[4 * i + 1], hva.y, a1);
                a2 = ffma2(w[4 * i + 2], hvb.x, a2);
                a3 = ffma2(w[4 * i + 3], hvb.y, a3);
            }
            float sum = (f2lo(a0) + f2hi(a0)) + (f2lo(a1) + f2hi(a1))
                      + (f2lo(a2) + f2hi(a2)) + (f2lo(a3) + f2hi(a3));
            sGHp[c][half][row] = sum;
            if (half == 0) sGI[c][row] = giv;

            if (is_gate_warp && gc == c) {
                bar_sync(1 + c, NTHREADS);   // wait: all partials ready
                const int p = base[c] + s - WARMUP;
                #pragma unroll
                for (int q = 0; q < 2; ++q) {
                    const int j = lane + q * 32;
                    float ghr = sGHp[c][0][j]       + sGHp[c][1][j]       + sBH[j];
                    float ghz = sGHp[c][0][64 + j]  + sGHp[c][1][64 + j]  + sBH[64 + j];
                    float ghn = sGHp[c][0][128 + j] + sGHp[c][1][128 + j] + sBH[128 + j];
                    float r_ = sig_(sGI[c][j]       + ghr);
                    float z_ = sig_(sGI[c][64 + j]  + ghz);
                    float n_ = th_ (sGI[c][128 + j] + r_ * ghn);
                    float hold = hbuf[ph][c][(int)rank * 64 + j];
                    float hn = (1.0f - z_) * n_ + z_ * hold;
                    if (p < 0) hn = 0.0f;   // pre-sequence region of segment 0

                    if (s + 1 < STEPS) {
                        uint32_t boff = (uint32_t)((((ph ^ 1) * CHAINS + c) << 8)
                                                   + (int)rank * 64 + j) * 4u;
                        uint32_t moff = (uint32_t)(c * 2 + (ph ^ 1)) * 8u;
                        #pragma unroll
                        for (int r = 0; r < 4; ++r)
                            st_async_f32(peer_hb[r] + boff, hn, peer_mb[r] + moff);
                    }

                    if (s >= WARMUP) {
                        if (enc) {
                            if ((p & 127) == 127) {
                                int t_out = p >> 7;
                                out[(size_t)t_out * H_ + rank * 64 + j] = hn;
                            }
                        } else {
                            int b = p & 127, t = p >> 7;
                            out[(size_t)(T_IN_ * H_) +
                                ((size_t)b * T_OUT_ + t) * H_ + rank * 64 + j] = hn;
                        }
                    }
                }
            } else {
                bar_arrive(1 + c, NTHREADS);  // publish partials, keep going
            }
        }
        if (s > 0) mph[ph]++;
    }

    cl_sync();   // drain async traffic before cluster teardown
}

// ============================================================
// launch
// ============================================================
extern "C" void kernel_launch(void* const* d_in, const int* in_sizes, int n_in,
                              void* d_out, int out_size)
{
    const float* x     = (const float*)d_in[0];
    const float* Wih_e = (const float*)d_in[1];
    const float* Whh_e = (const float*)d_in[2];
    const float* bih_e = (const float*)d_in[3];
    const float* bhh_e = (const float*)d_in[4];
    const float* Wih_d = (const float*)d_in[5];
    const float* Whh_d = (const float*)d_in[6];
    const float* bih_d = (const float*)d_in[7];
    const float* bhh_d = (const float*)d_in[8];
    float* out = (float*)d_out;

    dim3 ggrid(ENC_LEN / 64 + DEC_LEN / 64, G3_ / 64);  // (540, 12)
    gi_gemm<<<ggrid, 256>>>(x, Wih_e, bih_e, Wih_d, bih_d);

    gru_scan<<<(NCL_ENC + NCL_DEC) * 4, NTHREADS>>>(
        Whh_e, bhh_e, Whh_d, bhh_d, out);
}

// round 10
// speedup vs baseline: 2.7801x; 2.2456x over previous
#include <cuda_runtime.h>
#include <cstdint>

// ---------------- problem constants ----------------
#define B_      128
#define T_IN_   240
#define T_OUT_  30
#define D_      128
#define H_      256
#define G3_     768

#define ENC_LEN 30720   // T_IN * B
#define DEC_LEN 3840    // T_OUT * B

// segmentation: 3 chains per 4-CTA cluster
#define CHAINS   3
#define CHUNK    320     // 96 enc chains * 320 = 30720 ; 12 dec chains * 320 = 3840
#define WARMUP   96
#define STEPS    (CHUNK + WARMUP)   // 416
#define NCL_ENC  32
#define NCL_DEC  4

#define NTHREADS 384     // 12 warps

// ---------------- device scratch ----------------
__device__ float g_gi_enc[(size_t)ENC_LEN * G3_];   // ~94 MB
__device__ float g_gi_dec[(size_t)DEC_LEN * G3_];   // ~12 MB

// ---------------- helpers ----------------
__device__ __forceinline__ uint32_t smem_u32(const void* p) {
    return (uint32_t)__cvta_generic_to_shared(p);
}
__device__ __forceinline__ uint32_t mapa_u32(uint32_t addr, uint32_t rank) {
    uint32_t d;
    asm("mapa.shared::cluster.u32 %0, %1, %2;" : "=r"(d) : "r"(addr), "r"(rank));
    return d;
}
__device__ __forceinline__ void cl_sync() {
    asm volatile("barrier.cluster.arrive.aligned;" ::: "memory");
    asm volatile("barrier.cluster.wait.aligned;"   ::: "memory");
}
__device__ __forceinline__ void mbar_init(uint32_t mbar, uint32_t count) {
    asm volatile("mbarrier.init.shared.b64 [%0], %1;" :: "r"(mbar), "r"(count) : "memory");
}
__device__ __forceinline__ void mbar_arrive_expect(uint32_t mbar, uint32_t bytes) {
    asm volatile("mbarrier.arrive.expect_tx.shared::cta.b64 _, [%0], %1;"
                 :: "r"(mbar), "r"(bytes) : "memory");
}
__device__ __forceinline__ void mbar_wait_parity(uint32_t mbar, uint32_t parity) {
    uint32_t done;
    asm volatile(
        "{\n\t.reg .pred p;\n\t"
        "mbarrier.try_wait.parity.acquire.cta.shared::cta.b64 p, [%1], %2;\n\t"
        "selp.b32 %0, 1, 0, p;\n\t}"
        : "=r"(done) : "r"(mbar), "r"(parity) : "memory");
    if (!done) {
        asm volatile(
            "{\n\t.reg .pred P1;\n\t"
            "WAIT_LOOP_%=:\n\t"
            "mbarrier.try_wait.parity.acquire.cta.shared::cta.b64 P1, [%0], %1, 0x989680;\n\t"
            "@P1 bra.uni WAIT_DONE_%=;\n\t"
            "bra.uni WAIT_LOOP_%=;\n\t"
            "WAIT_DONE_%=:\n\t}"
            :: "r"(mbar), "r"(parity) : "memory");
    }
}
__device__ __forceinline__ void st_async_f32(uint32_t addr, float v, uint32_t mbar) {
    asm volatile(
        "st.async.weak.shared::cluster.mbarrier::complete_tx::bytes.f32 [%0], %1, [%2];"
        :: "r"(addr), "f"(v), "r"(mbar) : "memory");
}
__device__ __forceinline__ unsigned long long ffma2(unsigned long long a,
                                                    unsigned long long b,
                                                    unsigned long long c) {
    unsigned long long r;
    asm("fma.rn.f32x2 %0, %1, %2, %3;" : "=l"(r) : "l"(a), "l"(b), "l"(c));
    return r;
}
__device__ __forceinline__ float f2lo(unsigned long long v) {
    return __uint_as_float((unsigned)(v & 0xffffffffull));
}
__device__ __forceinline__ float f2hi(unsigned long long v) {
    return __uint_as_float((unsigned)(v >> 32));
}
__device__ __forceinline__ float tanh_ap(float x) {
    float y;
    asm("tanh.approx.f32 %0, %1;" : "=f"(y) : "f"(x));
    return y;
}
__device__ __forceinline__ float sig_(float x) { return 0.5f * tanh_ap(0.5f * x) + 0.5f; }
__device__ __forceinline__ float th_(float x)  { return tanh_ap(x); }

// ============================================================
// Phase 1: GI = X @ Wih^T + bih  (unchanged — verified)
// ============================================================
__global__ __launch_bounds__(256)
void gi_gemm(const float* __restrict__ x,
             const float* __restrict__ Wih_e, const float* __restrict__ bih_e,
             const float* __restrict__ Wih_d, const float* __restrict__ bih_d)
{
    __shared__ float Xs[64][68];   // [k][pos]
    __shared__ float Ws[64][68];   // [k][gate]

    const int tileP = blockIdx.x;
    const bool enc = (tileP < (ENC_LEN / 64));
    const float* __restrict__ Wih = enc ? Wih_e : Wih_d;
    const float* __restrict__ bih = enc ? bih_e : bih_d;
    float* __restrict__ gout = enc ? g_gi_enc : g_gi_dec;
    const int p0 = (enc ? tileP : (tileP - ENC_LEN / 64)) * 64;
    const int g0 = blockIdx.y * 64;
    const int tid = threadIdx.x;
    const int tstride = enc ? 1 : 8;

    const int tx = tid & 15;
    const int ty = tid >> 4;
    float acc[4][4] = {};

    for (int kc = 0; kc < 2; ++kc) {
        #pragma unroll
        for (int i = tid; i < 64 * 64; i += 256) {
            int pos = i >> 6, k = i & 63;
            int p = p0 + pos;
            int b = p & 127, t = (p >> 7) * tstride;
            Xs[k][pos] = x[((size_t)b * T_IN_ + t) * D_ + kc * 64 + k];
        }
        #pragma unroll
        for (int i = tid; i < 64 * 64; i += 256) {
            int g = i >> 6, k = i & 63;
            Ws[k][g] = Wih[(size_t)(g0 + g) * D_ + kc * 64 + k];
        }
        __syncthreads();

        #pragma unroll 16
        for (int k = 0; k < 64; ++k) {
            float4 a = *(const float4*)&Xs[k][ty * 4];
            float4 b = *(const float4*)&Ws[k][tx * 4];
            float av[4] = {a.x, a.y, a.z, a.w};
            float bv[4] = {b.x, b.y, b.z, b.w};
            #pragma unroll
            for (int i = 0; i < 4; ++i)
                #pragma unroll
                for (int j = 0; j < 4; ++j)
                    acc[i][j] = fmaf(av[i], bv[j], acc[i][j]);
        }
        __syncthreads();
    }

    float bz[4];
    #pragma unroll
    for (int j = 0; j < 4; ++j) bz[j] = bih[g0 + tx * 4 + j];

    #pragma unroll
    for (int i = 0; i < 4; ++i) {
        int p = p0 + ty * 4 + i;
        float4 o;
        o.x = acc[i][0] + bz[0];
        o.y = acc[i][1] + bz[1];
        o.z = acc[i][2] + bz[2];
        o.w = acc[i][3] + bz[3];
        *(float4*)&gout[(size_t)p * G3_ + g0 + tx * 4] = o;
    }
}

// ============================================================
// Phase 2: segmented GRU scan — 3 chains per step, ONE exchange.
//   warps 0-5  : rows 0..191, half 0 (h[0..127])  broadcast LDS
//   warps 6-11 : rows 0..191, half 1 (h[128..255])
// Per step: wait(mb[ph]) -> arm(mb[ph]) -> 3 matvecs ->
// __syncthreads -> gates on 192 threads -> st.async (one barrier).
// Arm strictly AFTER the wait on the same barrier (single arrive
// per phase — fixes R9's over-arrive race). No early remote store
// can hit the armed phase: remote step-(s+1) stores require OUR
// step-s stores, which follow our syncthreads, which follows arm.
// ============================================================
__global__ __launch_bounds__(NTHREADS, 1) __cluster_dims__(4, 1, 1)
void gru_scan(const float* __restrict__ Whh_e, const float* __restrict__ bhh_e,
              const float* __restrict__ Whh_d, const float* __restrict__ bhh_d,
              float* __restrict__ out)
{
    __shared__ __align__(16) float hbuf[2][CHAINS][256];   // [parity][chain][H]
    __shared__ float sGHp[CHAINS][2][192];                 // [chain][half][row]
    __shared__ float sGI[CHAINS][192];
    __shared__ float sBH[192];
    __shared__ __align__(8) unsigned long long mbars[2];   // one per parity

    const int tid  = threadIdx.x;
    const int warp = tid >> 5;
    const int lane = tid & 31;
    uint32_t rank;
    asm("mov.u32 %0, %%cluster_ctarank;" : "=r"(rank));

    const int cl   = blockIdx.x >> 2;
    const bool enc = cl < NCL_ENC;
    const int lcl  = enc ? cl : cl - NCL_ENC;
    const float* __restrict__ Whh = enc ? Whh_e : Whh_d;
    const float* __restrict__ bhh = enc ? bhh_e : bhh_d;
    const float* __restrict__ gi  = enc ? g_gi_enc : g_gi_dec;

    int base[CHAINS];
    #pragma unroll
    for (int c = 0; c < CHAINS; ++c)
        base[c] = (lcl * CHAINS + c) * CHUNK;

    const uint32_t mb_base = smem_u32(&mbars[0]);

    // ---- shared init ----
    for (int i = tid; i < 2 * CHAINS * 256; i += NTHREADS)
        ((float*)hbuf)[i] = 0.0f;
    if (tid < 192) {
        int g = tid >> 6, j = tid & 63;
        sBH[tid] = bhh[g * 256 + (int)rank * 64 + j];
    }
    if (tid == 0) {
        mbar_init(mb_base, 1);
        mbar_init(mb_base + 8, 1);
        // pre-arm mb[1]: it receives step-0 stores (3 chains x 4 ranks x 256B)
        mbar_arrive_expect(mb_base + 8, 1024 * CHAINS);
    }
    __syncthreads();
    cl_sync();   // barriers + zeroed buffers visible cluster-wide

    // ---- thread mapping ----
    const int half = (warp >= 6) ? 1 : 0;
    const int row  = ((half ? warp - 6 : warp) << 5) + lane;   // 0..191
    const int gate = row >> 6;
    const int jl   = row & 63;
    const int Rg   = gate * 256 + (int)rank * 64 + jl;

    // 128 weights in registers (64 packed f32x2)
    unsigned long long w[64];
    {
        const ulonglong2* wsrc =
            (const ulonglong2*)(Whh + (size_t)Rg * H_ + half * 128);
        #pragma unroll
        for (int i = 0; i < 32; ++i) {
            ulonglong2 t = wsrc[i];
            w[2 * i]     = t.x;
            w[2 * i + 1] = t.y;
        }
    }

    // peer addresses
    uint32_t peer_hb[4], peer_mb[4];
    {
        uint32_t my_hb = smem_u32(&hbuf[0][0][0]);
        #pragma unroll
        for (int r = 0; r < 4; ++r) {
            peer_hb[r] = mapa_u32(my_hb, r);
            peer_mb[r] = mapa_u32(mb_base, r);
        }
    }

    // per-chain gi pointers (half-0 threads prefetch one step ahead)
    const size_t gi_off = (size_t)gate * 256 + rank * 64 + jl;
    const float* gp[CHAINS];
    float gin[CHAINS];
    #pragma unroll
    for (int c = 0; c < CHAINS; ++c) {
        int p0 = base[c] - WARMUP; if (p0 < 0) p0 = 0;
        gp[c] = gi + (size_t)p0 * G3_ + gi_off;
        gin[c] = (half == 0) ? __ldg(gp[c]) : 0.0f;
    }

    uint32_t mph[2] = {0u, 0u};

    for (int s = 0; s < STEPS; ++s) {
        const int ph = s & 1;

        // wait for all chains' h(s) (stored at end of step s-1)
        if (s > 0) {
            mbar_wait_parity(mb_base + ph * 8, mph[ph] & 1u);
            mph[ph]++;
        }

        // arm mb[ph] for step (s+1)'s stores — AFTER the wait, so this is
        // the unique arrive of the fresh phase (no over-arrive race).
        if (tid == 0 && s + 1 < STEPS)
            mbar_arrive_expect(mb_base + ph * 8, 1024 * CHAINS);

        // ---- 3 matvecs back-to-back (no barriers between) ----
        #pragma unroll
        for (int c = 0; c < CHAINS; ++c) {
            float giv = gin[c];
            if (half == 0 && s + 1 < STEPS) {      // guarded prefetch
                if (base[c] + s + 1 > WARMUP) gp[c] += G3_;
                gin[c] = __ldg(gp[c]);
            }

            const ulonglong2* h2 =
                (const ulonglong2*)(&hbuf[ph][c][0] + (half << 7));
            unsigned long long a0 = 0ull, a1 = 0ull, a2 = 0ull, a3 = 0ull;
            #pragma unroll
            for (int i = 0; i < 16; ++i) {
                ulonglong2 hva = h2[2 * i];
                ulonglong2 hvb = h2[2 * i + 1];
                a0 = ffma2(w[4 * i],     hva.x, a0);
                a1 = ffma2(w[4 * i + 1], hva.y, a1);
                a2 = ffma2(w[4 * i + 2], hvb.x, a2);
                a3 = ffma2(w[4 * i + 3], hvb.y, a3);
            }
            float sum = (f2lo(a0) + f2hi(a0)) + (f2lo(a1) + f2hi(a1))
                      + (f2lo(a2) + f2hi(a2)) + (f2lo(a3) + f2hi(a3));
            sGHp[c][half][row] = sum;
            if (half == 0) sGI[c][row] = giv;
        }
        __syncthreads();   // all partials visible; arm ordered before stores

        // ---- gates: 192 threads = 3 chains x 64 coords, in parallel ----
        if (tid < 64 * CHAINS) {
            const int c = tid >> 6;
            const int j = tid & 63;
            const int p = base[c] + s - WARMUP;

            float ghr = sGHp[c][0][j]       + sGHp[c][1][j]       + sBH[j];
            float ghz = sGHp[c][0][64 + j]  + sGHp[c][1][64 + j]  + sBH[64 + j];
            float ghn = sGHp[c][0][128 + j] + sGHp[c][1][128 + j] + sBH[128 + j];
            float r_ = sig_(sGI[c][j]       + ghr);
            float z_ = sig_(sGI[c][64 + j]  + ghz);
            float n_ = th_ (sGI[c][128 + j] + r_ * ghn);
            float hold = hbuf[ph][c][(int)rank * 64 + j];
            float hn = (1.0f - z_) * n_ + z_ * hold;
            if (p < 0) hn = 0.0f;   // pre-sequence region of segment 0

            if (s + 1 < STEPS) {
                uint32_t boff = (uint32_t)((((ph ^ 1) * CHAINS + c) << 8)
                                           + (int)rank * 64 + j) * 4u;
                uint32_t moff = (uint32_t)(ph ^ 1) * 8u;
                #pragma unroll
                for (int r = 0; r < 4; ++r)
                    st_async_f32(peer_hb[r] + boff, hn, peer_mb[r] + moff);
            }

            if (s >= WARMUP) {
                if (enc) {
                    if ((p & 127) == 127) {
                        int t_out = p >> 7;
                        out[(size_t)t_out * H_ + rank * 64 + j] = hn;
                    }
                } else {
                    int b = p & 127, t = p >> 7;
                    out[(size_t)(T_IN_ * H_) +
                        ((size_t)b * T_OUT_ + t) * H_ + rank * 64 + j] = hn;
                }
            }
        }
        // no trailing barrier: the next step's mbar wait provides data
        // ordering (h arrivals) and sGHp/hbuf WAR protection (remote
        // stores require our stores, issued after our reads).
    }

    cl_sync();   // drain async traffic before cluster teardown
}

// ============================================================
// launch
// ============================================================
extern "C" void kernel_launch(void* const* d_in, const int* in_sizes, int n_in,
                              void* d_out, int out_size)
{
    const float* x     = (const float*)d_in[0];
    const float* Wih_e = (const float*)d_in[1];
    const float* Whh_e = (const float*)d_in[2];
    const float* bih_e = (const float*)d_in[3];
    const float* bhh_e = (const float*)d_in[4];
    const float* Wih_d = (const float*)d_in[5];
    const float* Whh_d = (const float*)d_in[6];
    const float* bih_d = (const float*)d_in[7];
    const float* bhh_d = (const float*)d_in[8];
    float* out = (float*)d_out;

    dim3 ggrid(ENC_LEN / 64 + DEC_LEN / 64, G3_ / 64);  // (540, 12)
    gi_gemm<<<ggrid, 256>>>(x, Wih_e, bih_e, Wih_d, bih_d);

    gru_scan<<<(NCL_ENC + NCL_DEC) * 4, NTHREADS>>>(
        Whh_e, bhh_e, Whh_d, bhh_d, out);
}